// round 4
// baseline (speedup 1.0000x reference)
#include <cuda_runtime.h>
#include <math.h>
#include <stdint.h>

// Problem constants
#define N_B   4
#define T_S   2048
#define D_M   1024
#define H_N   16
#define DH    64
#define MROWS (N_B * T_S)   // 8192

// ---------------------------------------------------------------------------
// Scratch (alloc-free rule: __device__ globals)
// ---------------------------------------------------------------------------
__device__ float g_Q  [(size_t)MROWS * D_M];
__device__ float g_K  [(size_t)MROWS * D_M];
__device__ float g_V  [(size_t)MROWS * D_M];
__device__ float g_ctx[(size_t)MROWS * D_M];

// ---------------------------------------------------------------------------
// SGEMM: C[m][n] = sum_k A[m][k] * B[n][k] + bias[n]
// A: [M,K] row-major, B: [Nc,K] row-major (i.e. computes A @ B^T + bias)
// Tiles: BM=BN=128, BK=16, 256 threads, 8x8 per-thread, double-buffered smem.
// smem stored k-major with stride 132 (pad 4) -> conflict-free LDS.128 reads.
// ---------------------------------------------------------------------------
__global__ __launch_bounds__(256, 2)
void sgemm_tn_bias(const float* __restrict__ A, const float* __restrict__ B,
                   const float* __restrict__ bias, float* __restrict__ C,
                   int M, int Nc, int K)
{
    __shared__ float As[2][16][132];
    __shared__ float Bs[2][16][132];

    const int tid = threadIdx.x;
    const int tx  = tid & 15;        // col group
    const int ty  = tid >> 4;        // row group
    const int m0  = blockIdx.y * 128;
    const int n0  = blockIdx.x * 128;

    const int lrow = tid >> 2;         // 0..63
    const int lk4  = (tid & 3) * 4;    // 0,4,8,12

    const float* Ap = A + (size_t)(m0 + lrow) * K + lk4;
    const float* Bp = B + (size_t)(n0 + lrow) * K + lk4;

    float acc[8][8];
    #pragma unroll
    for (int i = 0; i < 8; ++i)
        #pragma unroll
        for (int j = 0; j < 8; ++j) acc[i][j] = 0.0f;

    // prologue: load tile 0 into buffer 0
    float4 a0 = *(const float4*)Ap;
    float4 a1 = *(const float4*)(Ap + (size_t)64 * K);
    float4 b0 = *(const float4*)Bp;
    float4 b1 = *(const float4*)(Bp + (size_t)64 * K);
    #pragma unroll
    for (int j = 0; j < 4; ++j) {
        As[0][lk4 + j][lrow]      = ((const float*)&a0)[j];
        As[0][lk4 + j][lrow + 64] = ((const float*)&a1)[j];
        Bs[0][lk4 + j][lrow]      = ((const float*)&b0)[j];
        Bs[0][lk4 + j][lrow + 64] = ((const float*)&b1)[j];
    }
    __syncthreads();

    const int nt = K >> 4;
    for (int t = 0; t < nt; ++t) {
        const int cur = t & 1;

        if (t + 1 < nt) {
            const float* Ap2 = Ap + (t + 1) * 16;
            const float* Bp2 = Bp + (t + 1) * 16;
            a0 = *(const float4*)Ap2;
            a1 = *(const float4*)(Ap2 + (size_t)64 * K);
            b0 = *(const float4*)Bp2;
            b1 = *(const float4*)(Bp2 + (size_t)64 * K);
        }

        #pragma unroll
        for (int k = 0; k < 16; ++k) {
            float4 qa = *(const float4*)&As[cur][k][ty * 8];
            float4 qb = *(const float4*)&As[cur][k][ty * 8 + 4];
            float4 ra = *(const float4*)&Bs[cur][k][tx * 8];
            float4 rb = *(const float4*)&Bs[cur][k][tx * 8 + 4];
            float av[8] = {qa.x, qa.y, qa.z, qa.w, qb.x, qb.y, qb.z, qb.w};
            float bv[8] = {ra.x, ra.y, ra.z, ra.w, rb.x, rb.y, rb.z, rb.w};
            #pragma unroll
            for (int i = 0; i < 8; ++i)
                #pragma unroll
                for (int j = 0; j < 8; ++j)
                    acc[i][j] += av[i] * bv[j];
        }

        if (t + 1 < nt) {
            const int nxt = cur ^ 1;
            #pragma unroll
            for (int j = 0; j < 4; ++j) {
                As[nxt][lk4 + j][lrow]      = ((const float*)&a0)[j];
                As[nxt][lk4 + j][lrow + 64] = ((const float*)&a1)[j];
                Bs[nxt][lk4 + j][lrow]      = ((const float*)&b0)[j];
                Bs[nxt][lk4 + j][lrow + 64] = ((const float*)&b1)[j];
            }
            __syncthreads();
        }
    }

    // epilogue: add bias, write C
    float bcol[8];
    #pragma unroll
    for (int j = 0; j < 8; ++j) bcol[j] = bias[n0 + tx * 8 + j];

    #pragma unroll
    for (int i = 0; i < 8; ++i) {
        float* Cp = C + (size_t)(m0 + ty * 8 + i) * Nc + n0 + tx * 8;
        float4 o0 = make_float4(acc[i][0] + bcol[0], acc[i][1] + bcol[1],
                                acc[i][2] + bcol[2], acc[i][3] + bcol[3]);
        float4 o1 = make_float4(acc[i][4] + bcol[4], acc[i][5] + bcol[5],
                                acc[i][6] + bcol[6], acc[i][7] + bcol[7]);
        *(float4*)Cp       = o0;
        *(float4*)(Cp + 4) = o1;
    }
}

// ---------------------------------------------------------------------------
// Flash attention, fp32. One block per (n, h, 128-query tile).
// Streams 128-key tiles; online softmax; P staged through smem for PV GEMM.
// Mask semantics: mask[n][t]==0 masks the WHOLE query row to a constant ->
// softmax is exactly uniform; we get that by using row_scale = 0 (scores = 0).
// ---------------------------------------------------------------------------
#define SM_Q (64 * 132)    // Qs transposed [k][r], pad 4
#define SM_K (64 * 132)    // Ks transposed [k][c]
#define SM_V (128 * 68)    // Vs natural   [c][dh], pad 4
#define SM_P (128 * 132)   // Ps natural   [r][c],  pad 4
#define ATT_SMEM_FLOATS (SM_Q + SM_K + SM_V + SM_P)
#define ATT_SMEM_BYTES  (ATT_SMEM_FLOATS * 4)

__device__ __forceinline__ float rmax16(float v) {
    v = fmaxf(v, __shfl_xor_sync(0xffffffffu, v, 8));
    v = fmaxf(v, __shfl_xor_sync(0xffffffffu, v, 4));
    v = fmaxf(v, __shfl_xor_sync(0xffffffffu, v, 2));
    v = fmaxf(v, __shfl_xor_sync(0xffffffffu, v, 1));
    return v;
}
__device__ __forceinline__ float rsum16(float v) {
    v += __shfl_xor_sync(0xffffffffu, v, 8);
    v += __shfl_xor_sync(0xffffffffu, v, 4);
    v += __shfl_xor_sync(0xffffffffu, v, 2);
    v += __shfl_xor_sync(0xffffffffu, v, 1);
    return v;
}

__global__ __launch_bounds__(256, 1)
void flash_attn(const float* __restrict__ Q, const float* __restrict__ K,
                const float* __restrict__ V, const int* __restrict__ mask,
                float* __restrict__ ctx)
{
    extern __shared__ float sm[];
    float* Qs = sm;
    float* Ks = Qs + SM_Q;
    float* Vs = Ks + SM_K;
    float* Ps = Vs + SM_V;

    const int tid = threadIdx.x;
    const int tx  = tid & 15;
    const int ty  = tid >> 4;
    const int t0  = blockIdx.x * 128;
    const int h   = blockIdx.y;
    const int n   = blockIdx.z;

    const int kq = (tid & 15) * 4;  // k float4 offset (0..60)
    const int rb = tid >> 4;        // row base (0..15)

    // --- load Q tile, transposed into Qs[k][r] ---
    const float* Qg = Q + (size_t)(n * T_S + t0) * D_M + h * DH;
    #pragma unroll
    for (int rr = 0; rr < 8; ++rr) {
        int r = rb + rr * 16;
        float4 q = *(const float4*)(Qg + (size_t)r * D_M + kq);
        Qs[(kq + 0) * 132 + r] = q.x;
        Qs[(kq + 1) * 132 + r] = q.y;
        Qs[(kq + 2) * 132 + r] = q.z;
        Qs[(kq + 3) * 132 + r] = q.w;
    }

    // per-row mask scale: 1/sqrt(DH)=0.125 if visible, 0 if masked (uniform row)
    float rsc[8];
    #pragma unroll
    for (int i = 0; i < 8; ++i)
        rsc[i] = (mask[n * T_S + t0 + ty * 8 + i] != 0) ? 0.125f : 0.0f;

    float Oacc[8][4];
    float mrow[8], lrow[8];
    #pragma unroll
    for (int i = 0; i < 8; ++i) {
        mrow[i] = -1e30f; lrow[i] = 0.0f;
        #pragma unroll
        for (int u = 0; u < 4; ++u) Oacc[i][u] = 0.0f;
    }

    for (int s0 = 0; s0 < T_S; s0 += 128) {
        __syncthreads();   // Qs visible (first iter) / previous PV done (Ks,Vs,Ps reuse)

        // --- load K tile (transposed) and V tile (natural) ---
        const float* Kg = K + (size_t)(n * T_S + s0) * D_M + h * DH;
        const float* Vg = V + (size_t)(n * T_S + s0) * D_M + h * DH;
        #pragma unroll
        for (int rr = 0; rr < 8; ++rr) {
            int c = rb + rr * 16;
            float4 kv = *(const float4*)(Kg + (size_t)c * D_M + kq);
            Ks[(kq + 0) * 132 + c] = kv.x;
            Ks[(kq + 1) * 132 + c] = kv.y;
            Ks[(kq + 2) * 132 + c] = kv.z;
            Ks[(kq + 3) * 132 + c] = kv.w;
            float4 vv = *(const float4*)(Vg + (size_t)c * D_M + kq);
            *(float4*)&Vs[c * 68 + kq] = vv;
        }
        __syncthreads();

        // --- S = Q K^T  (8x8 per thread) ---
        float sacc[8][8];
        #pragma unroll
        for (int i = 0; i < 8; ++i)
            #pragma unroll
            for (int j = 0; j < 8; ++j) sacc[i][j] = 0.0f;

        #pragma unroll 8
        for (int k = 0; k < 64; ++k) {
            float4 qa = *(const float4*)&Qs[k * 132 + ty * 8];
            float4 qb = *(const float4*)&Qs[k * 132 + ty * 8 + 4];
            float4 ka = *(const float4*)&Ks[k * 132 + tx * 8];
            float4 kb = *(const float4*)&Ks[k * 132 + tx * 8 + 4];
            float av[8] = {qa.x, qa.y, qa.z, qa.w, qb.x, qb.y, qb.z, qb.w};
            float bv[8] = {ka.x, ka.y, ka.z, ka.w, kb.x, kb.y, kb.z, kb.w};
            #pragma unroll
            for (int i = 0; i < 8; ++i)
                #pragma unroll
                for (int j = 0; j < 8; ++j)
                    sacc[i][j] += av[i] * bv[j];
        }

        // --- online softmax per row (row = 16 lanes sharing ty) ---
        #pragma unroll
        for (int i = 0; i < 8; ++i) {
            const float sc = rsc[i];
            float sv[8];
            float mx = -1e30f;
            #pragma unroll
            for (int j = 0; j < 8; ++j) {
                sv[j] = sacc[i][j] * sc;
                mx = fmaxf(mx, sv[j]);
            }
            mx = rmax16(mx);
            const float mn = fmaxf(mrow[i], mx);
            const float cf = __expf(mrow[i] - mn);   // 0 on first tile (-1e30)
            float rs = 0.0f;
            #pragma unroll
            for (int j = 0; j < 8; ++j) {
                float p = __expf(sv[j] - mn);
                sv[j] = p;
                rs += p;
            }
            rs = rsum16(rs);
            mrow[i] = mn;
            lrow[i] = lrow[i] * cf + rs;
            #pragma unroll
            for (int u = 0; u < 4; ++u) Oacc[i][u] *= cf;

            *(float4*)&Ps[(ty * 8 + i) * 132 + tx * 8]     =
                make_float4(sv[0], sv[1], sv[2], sv[3]);
            *(float4*)&Ps[(ty * 8 + i) * 132 + tx * 8 + 4] =
                make_float4(sv[4], sv[5], sv[6], sv[7]);
        }
        __syncthreads();

        // --- O += P @ V  (rows ty*8+i, cols tx*4..tx*4+3) ---
        #pragma unroll 4
        for (int kk = 0; kk < 128; ++kk) {
            float4 v = *(const float4*)&Vs[kk * 68 + tx * 4];
            #pragma unroll
            for (int i = 0; i < 8; ++i) {
                float p = Ps[(ty * 8 + i) * 132 + kk];
                Oacc[i][0] += p * v.x;
                Oacc[i][1] += p * v.y;
                Oacc[i][2] += p * v.z;
                Oacc[i][3] += p * v.w;
            }
        }
    }

    // --- epilogue: normalize and write ctx in [N,T,D] layout ---
    #pragma unroll
    for (int i = 0; i < 8; ++i) {
        float inv = 1.0f / lrow[i];
        float4 o = make_float4(Oacc[i][0] * inv, Oacc[i][1] * inv,
                               Oacc[i][2] * inv, Oacc[i][3] * inv);
        *(float4*)(ctx + (size_t)(n * T_S + t0 + ty * 8 + i) * D_M
                        + h * DH + tx * 4) = o;
    }
}

// ---------------------------------------------------------------------------
// Launch
// ---------------------------------------------------------------------------
extern "C" void kernel_launch(void* const* d_in, const int* in_sizes, int n_in,
                              void* d_out, int out_size)
{
    (void)in_sizes; (void)n_in; (void)out_size;

    const float* query = (const float*)d_in[0];
    const int*   mask  = (const int*)  d_in[1];
    const float* Wq    = (const float*)d_in[2];
    const float* bq    = (const float*)d_in[3];
    const float* Wk    = (const float*)d_in[4];
    const float* bk    = (const float*)d_in[5];
    const float* Wv    = (const float*)d_in[6];
    const float* bv    = (const float*)d_in[7];
    const float* Wo    = (const float*)d_in[8];
    const float* bo    = (const float*)d_in[9];
    float* out = (float*)d_out;

    float *Qd, *Kd, *Vd, *Cd;
    cudaGetSymbolAddress((void**)&Qd, g_Q);
    cudaGetSymbolAddress((void**)&Kd, g_K);
    cudaGetSymbolAddress((void**)&Vd, g_V);
    cudaGetSymbolAddress((void**)&Cd, g_ctx);

    cudaFuncSetAttribute(flash_attn,
                         cudaFuncAttributeMaxDynamicSharedMemorySize,
                         ATT_SMEM_BYTES);

    dim3 gemm_grid(D_M / 128, MROWS / 128);  // (8, 64)

    sgemm_tn_bias<<<gemm_grid, 256>>>(query, Wq, bq, Qd, MROWS, D_M, D_M);
    sgemm_tn_bias<<<gemm_grid, 256>>>(query, Wk, bk, Kd, MROWS, D_M, D_M);
    sgemm_tn_bias<<<gemm_grid, 256>>>(query, Wv, bv, Vd, MROWS, D_M, D_M);

    flash_attn<<<dim3(T_S / 128, H_N, N_B), 256, ATT_SMEM_BYTES>>>(
        Qd, Kd, Vd, mask, Cd);

    sgemm_tn_bias<<<gemm_grid, 256>>>(Cd, Wo, bo, out, MROWS, D_M, D_M);
}

// round 6
// speedup vs baseline: 1.5293x; 1.5293x over previous
#include <cuda_runtime.h>
#include <math.h>
#include <stdint.h>

// Problem constants
#define N_B   4
#define T_S   2048
#define D_M   1024
#define H_N   16
#define DH    64
#define MROWS (N_B * T_S)   // 8192
#define GK    1024          // GEMM K

// ---------------------------------------------------------------------------
// Scratch (alloc-free rule: __device__ globals)
// ---------------------------------------------------------------------------
__device__ float g_Q  [(size_t)MROWS * D_M];
__device__ float g_K  [(size_t)MROWS * D_M];
__device__ float g_V  [(size_t)MROWS * D_M];
__device__ float g_ctx[(size_t)MROWS * D_M];

// ---------------------------------------------------------------------------
// Helpers (sm_100 plain target: NO tcgen05, NO a-suffix features)
// ---------------------------------------------------------------------------
__device__ __forceinline__ uint32_t smem_to_u32(const void* p) {
    uint32_t a;
    asm("{ .reg .u64 t; cvta.to.shared.u64 t, %1; cvt.u32.u64 %0, t; }"
        : "=r"(a) : "l"(p));
    return a;
}
__device__ __forceinline__ void cpa16(uint32_t dst, const void* src) {
    asm volatile("cp.async.cg.shared.global [%0], [%1], 16;"
                 :: "r"(dst), "l"(src) : "memory");
}
#define CP_COMMIT() asm volatile("cp.async.commit_group;" ::: "memory")

__device__ __forceinline__ uint32_t f2tf32(float x) {
    uint32_t y;
    asm("cvt.rna.tf32.f32 %0, %1;" : "=r"(y) : "f"(x));
    return y;
}
// D(16x8,f32) += A(16x8,tf32 row) * B(8x8,tf32 col)
__device__ __forceinline__ void mma_tf32(float* d, const uint32_t* a,
                                         const uint32_t* b) {
    asm volatile(
        "mma.sync.aligned.m16n8k8.row.col.f32.tf32.tf32.f32 "
        "{%0,%1,%2,%3}, {%4,%5,%6,%7}, {%8,%9}, {%0,%1,%2,%3};"
        : "+f"(d[0]), "+f"(d[1]), "+f"(d[2]), "+f"(d[3])
        : "r"(a[0]), "r"(a[1]), "r"(a[2]), "r"(a[3]),
          "r"(b[0]), "r"(b[1]));
}

// ---------------------------------------------------------------------------
// TF32 tensor-core SGEMM: C[m][n] = sum_k A[m][k]*B[n][k] + bias[n]
// A [M,K] rm, B [N,K] rm (computes A @ B^T + bias). M=8192, N=K=1024.
// 128x128x32 CTA tile, 256 thr = 8 warps (2 M x 4 N), warp tile 64x32.
// cp.async double-buffered smem; stride-36 pad => conflict-free fragment LDS.
// ---------------------------------------------------------------------------
#define TSTR 36                       // smem row stride (floats)
#define TILE_FLOATS (128 * TSTR)      // 4608
#define A_BYTES (TILE_FLOATS * 4)     // 18432
#define GEMM_SMEM_BYTES (4 * A_BYTES) // 73728: A0,A1,B0,B1

__global__ __launch_bounds__(256, 2)
void sgemm_tf32_mma(const float* __restrict__ A, const float* __restrict__ B,
                    const float* __restrict__ bias, float* __restrict__ C)
{
    extern __shared__ float sm[];
    const uint32_t sb = smem_to_u32(sm);
    const int tid  = threadIdx.x;
    const int wid  = tid >> 5;
    const int lane = tid & 31;
    const int g    = lane >> 2;      // group id 0..7
    const int tg   = lane & 3;       // thread-in-group 0..3
    const int warp_m = wid & 1;      // 0..1
    const int warp_n = wid >> 1;     // 0..3
    const int m0 = blockIdx.y * 128;
    const int n0 = blockIdx.x * 128;

    // cp.async mapping: thread -> (row lr + 32*i, 4-float col lc4)
    const int lr  = tid >> 3;                 // 0..31
    const int lc4 = (tid & 7) * 4;            // 0..28
    const uint32_t st_off = (uint32_t)((lr * TSTR + lc4) * 4);
    const float* Ag = A + (size_t)(m0 + lr) * GK + lc4;
    const float* Bg = B + (size_t)(n0 + lr) * GK + lc4;

    // prologue: k-tile 0 -> buffer 0
    #pragma unroll
    for (int i = 0; i < 4; ++i) {
        cpa16(sb + st_off + i * (32 * TSTR * 4), Ag + (size_t)(32 * i) * GK);
        cpa16(sb + 2 * A_BYTES + st_off + i * (32 * TSTR * 4),
              Bg + (size_t)(32 * i) * GK);
    }
    CP_COMMIT();

    float acc[4][4][4];
    #pragma unroll
    for (int mt = 0; mt < 4; ++mt)
        #pragma unroll
        for (int nt = 0; nt < 4; ++nt)
            #pragma unroll
            for (int u = 0; u < 4; ++u) acc[mt][nt][u] = 0.0f;

    const int NT = GK / 32;   // 32 k-tiles
    for (int kt = 0; kt < NT; ++kt) {
        const int buf = kt & 1;
        if (kt + 1 < NT) {
            const int nb = buf ^ 1;
            const float* Ag2 = Ag + (kt + 1) * 32;
            const float* Bg2 = Bg + (kt + 1) * 32;
            #pragma unroll
            for (int i = 0; i < 4; ++i) {
                cpa16(sb + nb * A_BYTES + st_off + i * (32 * TSTR * 4),
                      Ag2 + (size_t)(32 * i) * GK);
                cpa16(sb + 2 * A_BYTES + nb * A_BYTES + st_off + i * (32 * TSTR * 4),
                      Bg2 + (size_t)(32 * i) * GK);
            }
            CP_COMMIT();
            asm volatile("cp.async.wait_group 1;" ::: "memory");
        } else {
            asm volatile("cp.async.wait_group 0;" ::: "memory");
        }
        __syncthreads();

        const float* Asb = sm + buf * TILE_FLOATS;
        const float* Bsb = sm + 2 * TILE_FLOATS + buf * TILE_FLOATS;

        #pragma unroll
        for (int ks = 0; ks < 4; ++ks) {
            const int kc = ks * 8 + tg;
            uint32_t af[4][4], bf[4][2];
            #pragma unroll
            for (int mt = 0; mt < 4; ++mt) {
                const float* p = Asb + (warp_m * 64 + mt * 16 + g) * TSTR + kc;
                af[mt][0] = f2tf32(p[0]);            // (g,     tg)
                af[mt][1] = f2tf32(p[8 * TSTR]);     // (g+8,   tg)
                af[mt][2] = f2tf32(p[4]);            // (g,   tg+4)
                af[mt][3] = f2tf32(p[8 * TSTR + 4]); // (g+8, tg+4)
            }
            #pragma unroll
            for (int nt = 0; nt < 4; ++nt) {
                const float* p = Bsb + (warp_n * 32 + nt * 8 + g) * TSTR + kc;
                bf[nt][0] = f2tf32(p[0]);            // (k=tg,   n=g)
                bf[nt][1] = f2tf32(p[4]);            // (k=tg+4, n=g)
            }
            #pragma unroll
            for (int mt = 0; mt < 4; ++mt)
                #pragma unroll
                for (int nt = 0; nt < 4; ++nt)
                    mma_tf32(acc[mt][nt], af[mt], bf[nt]);
        }
        __syncthreads();
    }

    // epilogue: add bias, write C (fragment: c0/c1 row g, c2/c3 row g+8)
    #pragma unroll
    for (int nt = 0; nt < 4; ++nt) {
        const int col = n0 + warp_n * 32 + nt * 8 + tg * 2;
        const float b0 = bias[col], b1 = bias[col + 1];
        #pragma unroll
        for (int mt = 0; mt < 4; ++mt) {
            const int row = m0 + warp_m * 64 + mt * 16 + g;
            float2 v0 = make_float2(acc[mt][nt][0] + b0, acc[mt][nt][1] + b1);
            float2 v1 = make_float2(acc[mt][nt][2] + b0, acc[mt][nt][3] + b1);
            *(float2*)(C + (size_t)row * D_M + col)       = v0;
            *(float2*)(C + (size_t)(row + 8) * D_M + col) = v1;
        }
    }
}

// ---------------------------------------------------------------------------
// Flash attention, fp32 (unchanged from R4-passing version; next target).
// ---------------------------------------------------------------------------
#define SM_Q (64 * 132)
#define SM_K (64 * 132)
#define SM_V (128 * 68)
#define SM_P (128 * 132)
#define ATT_SMEM_FLOATS (SM_Q + SM_K + SM_V + SM_P)
#define ATT_SMEM_BYTES  (ATT_SMEM_FLOATS * 4)

__device__ __forceinline__ float rmax16(float v) {
    v = fmaxf(v, __shfl_xor_sync(0xffffffffu, v, 8));
    v = fmaxf(v, __shfl_xor_sync(0xffffffffu, v, 4));
    v = fmaxf(v, __shfl_xor_sync(0xffffffffu, v, 2));
    v = fmaxf(v, __shfl_xor_sync(0xffffffffu, v, 1));
    return v;
}
__device__ __forceinline__ float rsum16(float v) {
    v += __shfl_xor_sync(0xffffffffu, v, 8);
    v += __shfl_xor_sync(0xffffffffu, v, 4);
    v += __shfl_xor_sync(0xffffffffu, v, 2);
    v += __shfl_xor_sync(0xffffffffu, v, 1);
    return v;
}

__global__ __launch_bounds__(256, 1)
void flash_attn(const float* __restrict__ Q, const float* __restrict__ K,
                const float* __restrict__ V, const int* __restrict__ mask,
                float* __restrict__ ctx)
{
    extern __shared__ float sm[];
    float* Qs = sm;
    float* Ks = Qs + SM_Q;
    float* Vs = Ks + SM_K;
    float* Ps = Vs + SM_V;

    const int tid = threadIdx.x;
    const int tx  = tid & 15;
    const int ty  = tid >> 4;
    const int t0  = blockIdx.x * 128;
    const int h   = blockIdx.y;
    const int n   = blockIdx.z;

    const int kq = (tid & 15) * 4;
    const int rb = tid >> 4;

    const float* Qg = Q + (size_t)(n * T_S + t0) * D_M + h * DH;
    #pragma unroll
    for (int rr = 0; rr < 8; ++rr) {
        int r = rb + rr * 16;
        float4 q = *(const float4*)(Qg + (size_t)r * D_M + kq);
        Qs[(kq + 0) * 132 + r] = q.x;
        Qs[(kq + 1) * 132 + r] = q.y;
        Qs[(kq + 2) * 132 + r] = q.z;
        Qs[(kq + 3) * 132 + r] = q.w;
    }

    float rsc[8];
    #pragma unroll
    for (int i = 0; i < 8; ++i)
        rsc[i] = (mask[n * T_S + t0 + ty * 8 + i] != 0) ? 0.125f : 0.0f;

    float Oacc[8][4];
    float mrow[8], lrow[8];
    #pragma unroll
    for (int i = 0; i < 8; ++i) {
        mrow[i] = -1e30f; lrow[i] = 0.0f;
        #pragma unroll
        for (int u = 0; u < 4; ++u) Oacc[i][u] = 0.0f;
    }

    for (int s0 = 0; s0 < T_S; s0 += 128) {
        __syncthreads();

        const float* Kg = K + (size_t)(n * T_S + s0) * D_M + h * DH;
        const float* Vg = V + (size_t)(n * T_S + s0) * D_M + h * DH;
        #pragma unroll
        for (int rr = 0; rr < 8; ++rr) {
            int c = rb + rr * 16;
            float4 kv = *(const float4*)(Kg + (size_t)c * D_M + kq);
            Ks[(kq + 0) * 132 + c] = kv.x;
            Ks[(kq + 1) * 132 + c] = kv.y;
            Ks[(kq + 2) * 132 + c] = kv.z;
            Ks[(kq + 3) * 132 + c] = kv.w;
            float4 vv = *(const float4*)(Vg + (size_t)c * D_M + kq);
            *(float4*)&Vs[c * 68 + kq] = vv;
        }
        __syncthreads();

        float sacc[8][8];
        #pragma unroll
        for (int i = 0; i < 8; ++i)
            #pragma unroll
            for (int j = 0; j < 8; ++j) sacc[i][j] = 0.0f;

        #pragma unroll 8
        for (int k = 0; k < 64; ++k) {
            float4 qa = *(const float4*)&Qs[k * 132 + ty * 8];
            float4 qb = *(const float4*)&Qs[k * 132 + ty * 8 + 4];
            float4 ka = *(const float4*)&Ks[k * 132 + tx * 8];
            float4 kb = *(const float4*)&Ks[k * 132 + tx * 8 + 4];
            float av[8] = {qa.x, qa.y, qa.z, qa.w, qb.x, qb.y, qb.z, qb.w};
            float bv[8] = {ka.x, ka.y, ka.z, ka.w, kb.x, kb.y, kb.z, kb.w};
            #pragma unroll
            for (int i = 0; i < 8; ++i)
                #pragma unroll
                for (int j = 0; j < 8; ++j)
                    sacc[i][j] += av[i] * bv[j];
        }

        #pragma unroll
        for (int i = 0; i < 8; ++i) {
            const float sc = rsc[i];
            float sv[8];
            float mx = -1e30f;
            #pragma unroll
            for (int j = 0; j < 8; ++j) {
                sv[j] = sacc[i][j] * sc;
                mx = fmaxf(mx, sv[j]);
            }
            mx = rmax16(mx);
            const float mn = fmaxf(mrow[i], mx);
            const float cf = __expf(mrow[i] - mn);
            float rs = 0.0f;
            #pragma unroll
            for (int j = 0; j < 8; ++j) {
                float p = __expf(sv[j] - mn);
                sv[j] = p;
                rs += p;
            }
            rs = rsum16(rs);
            mrow[i] = mn;
            lrow[i] = lrow[i] * cf + rs;
            #pragma unroll
            for (int u = 0; u < 4; ++u) Oacc[i][u] *= cf;

            *(float4*)&Ps[(ty * 8 + i) * 132 + tx * 8]     =
                make_float4(sv[0], sv[1], sv[2], sv[3]);
            *(float4*)&Ps[(ty * 8 + i) * 132 + tx * 8 + 4] =
                make_float4(sv[4], sv[5], sv[6], sv[7]);
        }
        __syncthreads();

        #pragma unroll 4
        for (int kk = 0; kk < 128; ++kk) {
            float4 v = *(const float4*)&Vs[kk * 68 + tx * 4];
            #pragma unroll
            for (int i = 0; i < 8; ++i) {
                float p = Ps[(ty * 8 + i) * 132 + kk];
                Oacc[i][0] += p * v.x;
                Oacc[i][1] += p * v.y;
                Oacc[i][2] += p * v.z;
                Oacc[i][3] += p * v.w;
            }
        }
    }

    #pragma unroll
    for (int i = 0; i < 8; ++i) {
        float inv = 1.0f / lrow[i];
        float4 o = make_float4(Oacc[i][0] * inv, Oacc[i][1] * inv,
                               Oacc[i][2] * inv, Oacc[i][3] * inv);
        *(float4*)(ctx + (size_t)(n * T_S + t0 + ty * 8 + i) * D_M
                        + h * DH + tx * 4) = o;
    }
}

// ---------------------------------------------------------------------------
// Launch
// ---------------------------------------------------------------------------
extern "C" void kernel_launch(void* const* d_in, const int* in_sizes, int n_in,
                              void* d_out, int out_size)
{
    (void)in_sizes; (void)n_in; (void)out_size;

    const float* query = (const float*)d_in[0];
    const int*   mask  = (const int*)  d_in[1];
    const float* Wq    = (const float*)d_in[2];
    const float* bq    = (const float*)d_in[3];
    const float* Wk    = (const float*)d_in[4];
    const float* bk    = (const float*)d_in[5];
    const float* Wv    = (const float*)d_in[6];
    const float* bv    = (const float*)d_in[7];
    const float* Wo    = (const float*)d_in[8];
    const float* bo    = (const float*)d_in[9];
    float* out = (float*)d_out;

    float *Qd, *Kd, *Vd, *Cd;
    cudaGetSymbolAddress((void**)&Qd, g_Q);
    cudaGetSymbolAddress((void**)&Kd, g_K);
    cudaGetSymbolAddress((void**)&Vd, g_V);
    cudaGetSymbolAddress((void**)&Cd, g_ctx);

    cudaFuncSetAttribute(sgemm_tf32_mma,
                         cudaFuncAttributeMaxDynamicSharedMemorySize,
                         GEMM_SMEM_BYTES);
    cudaFuncSetAttribute(flash_attn,
                         cudaFuncAttributeMaxDynamicSharedMemorySize,
                         ATT_SMEM_BYTES);

    dim3 gemm_grid(D_M / 128, MROWS / 128);  // (8, 64)

    sgemm_tf32_mma<<<gemm_grid, 256, GEMM_SMEM_BYTES>>>(query, Wq, bq, Qd);
    sgemm_tf32_mma<<<gemm_grid, 256, GEMM_SMEM_BYTES>>>(query, Wk, bk, Kd);
    sgemm_tf32_mma<<<gemm_grid, 256, GEMM_SMEM_BYTES>>>(query, Wv, bv, Vd);

    flash_attn<<<dim3(T_S / 128, H_N, N_B), 256, ATT_SMEM_BYTES>>>(
        Qd, Kd, Vd, mask, Cd);

    sgemm_tf32_mma<<<gemm_grid, 256, GEMM_SMEM_BYTES>>>(Cd, Wo, bo, out);
}

// round 7
// speedup vs baseline: 2.3579x; 1.5417x over previous
#include <cuda_runtime.h>
#include <math.h>
#include <stdint.h>

// Problem constants
#define N_B   4
#define T_S   2048
#define D_M   1024
#define H_N   16
#define DH    64
#define MROWS (N_B * T_S)   // 8192
#define GK    1024          // GEMM K

// ---------------------------------------------------------------------------
// Scratch (alloc-free rule: __device__ globals)
// ---------------------------------------------------------------------------
__device__ float g_Q  [(size_t)MROWS * D_M];
__device__ float g_K  [(size_t)MROWS * D_M];
__device__ float g_V  [(size_t)MROWS * D_M];
__device__ float g_ctx[(size_t)MROWS * D_M];

// ---------------------------------------------------------------------------
// Helpers (sm_100 plain target: NO tcgen05)
// ---------------------------------------------------------------------------
__device__ __forceinline__ uint32_t smem_to_u32(const void* p) {
    uint32_t a;
    asm("{ .reg .u64 t; cvta.to.shared.u64 t, %1; cvt.u32.u64 %0, t; }"
        : "=r"(a) : "l"(p));
    return a;
}
__device__ __forceinline__ void cpa16(uint32_t dst, const void* src) {
    asm volatile("cp.async.cg.shared.global [%0], [%1], 16;"
                 :: "r"(dst), "l"(src) : "memory");
}
#define CP_COMMIT() asm volatile("cp.async.commit_group;" ::: "memory")

__device__ __forceinline__ uint32_t f2tf32(float x) {
    uint32_t y;
    asm("cvt.rna.tf32.f32 %0, %1;" : "=r"(y) : "f"(x));
    return y;
}
// D(16x8,f32) += A(16x8,tf32 row) * B(8x8,tf32 col)
__device__ __forceinline__ void mma_tf32(float* d, const uint32_t* a,
                                         const uint32_t* b) {
    asm volatile(
        "mma.sync.aligned.m16n8k8.row.col.f32.tf32.tf32.f32 "
        "{%0,%1,%2,%3}, {%4,%5,%6,%7}, {%8,%9}, {%0,%1,%2,%3};"
        : "+f"(d[0]), "+f"(d[1]), "+f"(d[2]), "+f"(d[3])
        : "r"(a[0]), "r"(a[1]), "r"(a[2]), "r"(a[3]),
          "r"(b[0]), "r"(b[1]));
}

// ---------------------------------------------------------------------------
// TF32 tensor-core SGEMM (validated in R6): C = A @ B^T + bias
// ---------------------------------------------------------------------------
#define TSTR 36
#define TILE_FLOATS (128 * TSTR)
#define A_BYTES (TILE_FLOATS * 4)
#define GEMM_SMEM_BYTES (4 * A_BYTES)

__global__ __launch_bounds__(256, 2)
void sgemm_tf32_mma(const float* __restrict__ A, const float* __restrict__ B,
                    const float* __restrict__ bias, float* __restrict__ C)
{
    extern __shared__ float sm[];
    const uint32_t sb = smem_to_u32(sm);
    const int tid  = threadIdx.x;
    const int wid  = tid >> 5;
    const int lane = tid & 31;
    const int g    = lane >> 2;
    const int tg   = lane & 3;
    const int warp_m = wid & 1;
    const int warp_n = wid >> 1;
    const int m0 = blockIdx.y * 128;
    const int n0 = blockIdx.x * 128;

    const int lr  = tid >> 3;
    const int lc4 = (tid & 7) * 4;
    const uint32_t st_off = (uint32_t)((lr * TSTR + lc4) * 4);
    const float* Ag = A + (size_t)(m0 + lr) * GK + lc4;
    const float* Bg = B + (size_t)(n0 + lr) * GK + lc4;

    #pragma unroll
    for (int i = 0; i < 4; ++i) {
        cpa16(sb + st_off + i * (32 * TSTR * 4), Ag + (size_t)(32 * i) * GK);
        cpa16(sb + 2 * A_BYTES + st_off + i * (32 * TSTR * 4),
              Bg + (size_t)(32 * i) * GK);
    }
    CP_COMMIT();

    float acc[4][4][4];
    #pragma unroll
    for (int mt = 0; mt < 4; ++mt)
        #pragma unroll
        for (int nt = 0; nt < 4; ++nt)
            #pragma unroll
            for (int u = 0; u < 4; ++u) acc[mt][nt][u] = 0.0f;

    const int NT = GK / 32;
    for (int kt = 0; kt < NT; ++kt) {
        const int buf = kt & 1;
        if (kt + 1 < NT) {
            const int nb = buf ^ 1;
            const float* Ag2 = Ag + (kt + 1) * 32;
            const float* Bg2 = Bg + (kt + 1) * 32;
            #pragma unroll
            for (int i = 0; i < 4; ++i) {
                cpa16(sb + nb * A_BYTES + st_off + i * (32 * TSTR * 4),
                      Ag2 + (size_t)(32 * i) * GK);
                cpa16(sb + 2 * A_BYTES + nb * A_BYTES + st_off + i * (32 * TSTR * 4),
                      Bg2 + (size_t)(32 * i) * GK);
            }
            CP_COMMIT();
            asm volatile("cp.async.wait_group 1;" ::: "memory");
        } else {
            asm volatile("cp.async.wait_group 0;" ::: "memory");
        }
        __syncthreads();

        const float* Asb = sm + buf * TILE_FLOATS;
        const float* Bsb = sm + 2 * TILE_FLOATS + buf * TILE_FLOATS;

        #pragma unroll
        for (int ks = 0; ks < 4; ++ks) {
            const int kc = ks * 8 + tg;
            uint32_t af[4][4], bf[4][2];
            #pragma unroll
            for (int mt = 0; mt < 4; ++mt) {
                const float* p = Asb + (warp_m * 64 + mt * 16 + g) * TSTR + kc;
                af[mt][0] = f2tf32(p[0]);
                af[mt][1] = f2tf32(p[8 * TSTR]);
                af[mt][2] = f2tf32(p[4]);
                af[mt][3] = f2tf32(p[8 * TSTR + 4]);
            }
            #pragma unroll
            for (int nt = 0; nt < 4; ++nt) {
                const float* p = Bsb + (warp_n * 32 + nt * 8 + g) * TSTR + kc;
                bf[nt][0] = f2tf32(p[0]);
                bf[nt][1] = f2tf32(p[4]);
            }
            #pragma unroll
            for (int mt = 0; mt < 4; ++mt)
                #pragma unroll
                for (int nt = 0; nt < 4; ++nt)
                    mma_tf32(acc[mt][nt], af[mt], bf[nt]);
        }
        __syncthreads();
    }

    #pragma unroll
    for (int nt = 0; nt < 4; ++nt) {
        const int col = n0 + warp_n * 32 + nt * 8 + tg * 2;
        const float b0 = bias[col], b1 = bias[col + 1];
        #pragma unroll
        for (int mt = 0; mt < 4; ++mt) {
            const int row = m0 + warp_m * 64 + mt * 16 + g;
            float2 v0 = make_float2(acc[mt][nt][0] + b0, acc[mt][nt][1] + b1);
            float2 v1 = make_float2(acc[mt][nt][2] + b0, acc[mt][nt][3] + b1);
            *(float2*)(C + (size_t)row * D_M + col)       = v0;
            *(float2*)(C + (size_t)(row + 8) * D_M + col) = v1;
        }
    }
}

// ---------------------------------------------------------------------------
// Flash attention on mma.sync tf32.
// Block = 256 thr = 8 warps; warp w owns q-rows [16w,16w+16) => warp-local
// softmax (full 128 score cols per warp; row reduce = 2 shfl over tg lanes).
// Q fragments live in registers for the whole block. K/V double-buffered
// cp.async smem (stride 68 => conflict-free fragment LDS). P staged in smem
// pre-converted to tf32 (warp-private rows => __syncwarp only).
// ---------------------------------------------------------------------------
#define KVSTR 68                          // floats per K/V smem row
#define KVW   (128 * KVSTR)               // 8704 floats per tile
#define PSTR  132
#define OFF_V (2 * KVW)
#define OFF_P (4 * KVW)
#define FA_SMEM_FLOATS (4 * KVW + 128 * PSTR)
#define FA_SMEM_BYTES  (FA_SMEM_FLOATS * 4)   // 206848

__global__ __launch_bounds__(256, 1)
void flash_attn_mma(const float* __restrict__ Q, const float* __restrict__ K,
                    const float* __restrict__ V, const int* __restrict__ mask,
                    float* __restrict__ ctx)
{
    extern __shared__ float sm[];
    const uint32_t sb = smem_to_u32(sm);
    float* Ps = sm + OFF_P;

    const int tid  = threadIdx.x;
    const int wid  = tid >> 5;
    const int lane = tid & 31;
    const int g    = lane >> 2;
    const int tg   = lane & 3;
    const int t0 = blockIdx.x * 128;
    const int h  = blockIdx.y;
    const int n  = blockIdx.z;

    // ---- Q fragments: rows (16w+g, 16w+g+8), k = 0..63, once per block ----
    const size_t qrow = (size_t)(n * T_S + t0 + wid * 16 + g);
    const float* Qp0 = Q + qrow * D_M + h * DH;
    const float* Qp1 = Qp0 + (size_t)8 * D_M;
    uint32_t qf[8][4];
    #pragma unroll
    for (int ks = 0; ks < 8; ++ks) {
        qf[ks][0] = f2tf32(Qp0[ks * 8 + tg]);
        qf[ks][1] = f2tf32(Qp1[ks * 8 + tg]);
        qf[ks][2] = f2tf32(Qp0[ks * 8 + tg + 4]);
        qf[ks][3] = f2tf32(Qp1[ks * 8 + tg + 4]);
    }

    const float rsc0 = (mask[n * T_S + t0 + wid * 16 + g]     != 0) ? 0.125f : 0.0f;
    const float rsc1 = (mask[n * T_S + t0 + wid * 16 + g + 8] != 0) ? 0.125f : 0.0f;

    float m0 = -1e30f, l0 = 0.0f, m1 = -1e30f, l1 = 0.0f;
    float oacc[8][4];
    #pragma unroll
    for (int nt = 0; nt < 8; ++nt)
        #pragma unroll
        for (int u = 0; u < 4; ++u) oacc[nt][u] = 0.0f;

    // ---- cp.async mapping: thread -> K/V row tid>>1, half tid&1 ----
    const int cr = tid >> 1, chf = tid & 1;
    const float* Kg = K + ((size_t)(n * T_S) + cr) * D_M + h * DH + chf * 32;
    const float* Vg = V + ((size_t)(n * T_S) + cr) * D_M + h * DH + chf * 32;
    const uint32_t cdst = (uint32_t)((cr * KVSTR + chf * 32) * 4);

    // prologue: tile 0 -> buffer 0
    #pragma unroll
    for (int j = 0; j < 8; ++j) {
        cpa16(sb + cdst + j * 16,                 Kg + j * 4);
        cpa16(sb + OFF_V * 4 + cdst + j * 16,     Vg + j * 4);
    }
    CP_COMMIT();

    for (int st = 0; st < T_S / 128; ++st) {
        const int buf = st & 1;
        asm volatile("cp.async.wait_group 0;" ::: "memory");
        __syncthreads();

        if (st + 1 < T_S / 128) {
            const int nb = buf ^ 1;
            const size_t go = (size_t)(st + 1) * 128 * D_M;
            #pragma unroll
            for (int j = 0; j < 8; ++j) {
                cpa16(sb + nb * KVW * 4 + cdst + j * 16,           Kg + go + j * 4);
                cpa16(sb + (OFF_V + nb * KVW) * 4 + cdst + j * 16, Vg + go + j * 4);
            }
            CP_COMMIT();
        }

        const float* Kb = sm + buf * KVW;
        const float* Vb = sm + OFF_V + buf * KVW;

        // ---- S = Q K^T : 16 n-tiles x 8 k-steps ----
        float sacc[16][4];
        #pragma unroll
        for (int nt = 0; nt < 16; ++nt)
            #pragma unroll
            for (int u = 0; u < 4; ++u) sacc[nt][u] = 0.0f;

        #pragma unroll
        for (int ks = 0; ks < 8; ++ks) {
            #pragma unroll
            for (int nt = 0; nt < 16; ++nt) {
                const float* kp = Kb + (nt * 8 + g) * KVSTR + ks * 8 + tg;
                uint32_t bf[2];
                bf[0] = f2tf32(kp[0]);
                bf[1] = f2tf32(kp[4]);
                mma_tf32(sacc[nt], qf[ks], bf);
            }
        }

        // ---- online softmax (rows g and g+8; reduce over tg lanes) ----
        {
            float mx0 = -1e30f, mx1 = -1e30f;
            #pragma unroll
            for (int nt = 0; nt < 16; ++nt) {
                sacc[nt][0] *= rsc0; sacc[nt][1] *= rsc0;
                sacc[nt][2] *= rsc1; sacc[nt][3] *= rsc1;
                mx0 = fmaxf(mx0, fmaxf(sacc[nt][0], sacc[nt][1]));
                mx1 = fmaxf(mx1, fmaxf(sacc[nt][2], sacc[nt][3]));
            }
            mx0 = fmaxf(mx0, __shfl_xor_sync(0xffffffffu, mx0, 1));
            mx0 = fmaxf(mx0, __shfl_xor_sync(0xffffffffu, mx0, 2));
            mx1 = fmaxf(mx1, __shfl_xor_sync(0xffffffffu, mx1, 1));
            mx1 = fmaxf(mx1, __shfl_xor_sync(0xffffffffu, mx1, 2));

            const float mn0 = fmaxf(m0, mx0), mn1 = fmaxf(m1, mx1);
            const float cf0 = __expf(m0 - mn0), cf1 = __expf(m1 - mn1);
            float rs0 = 0.0f, rs1 = 0.0f;

            uint32_t* Pr0 = (uint32_t*)&Ps[(wid * 16 + g) * PSTR + tg * 2];
            uint32_t* Pr1 = (uint32_t*)&Ps[(wid * 16 + g + 8) * PSTR + tg * 2];
            #pragma unroll
            for (int nt = 0; nt < 16; ++nt) {
                float p0 = __expf(sacc[nt][0] - mn0);
                float p1 = __expf(sacc[nt][1] - mn0);
                float p2 = __expf(sacc[nt][2] - mn1);
                float p3 = __expf(sacc[nt][3] - mn1);
                rs0 += p0 + p1;
                rs1 += p2 + p3;
                uint2 w0 = make_uint2(f2tf32(p0), f2tf32(p1));
                uint2 w1 = make_uint2(f2tf32(p2), f2tf32(p3));
                *(uint2*)(Pr0 + nt * 8) = w0;
                *(uint2*)(Pr1 + nt * 8) = w1;
            }
            rs0 += __shfl_xor_sync(0xffffffffu, rs0, 1);
            rs0 += __shfl_xor_sync(0xffffffffu, rs0, 2);
            rs1 += __shfl_xor_sync(0xffffffffu, rs1, 1);
            rs1 += __shfl_xor_sync(0xffffffffu, rs1, 2);

            m0 = mn0; l0 = l0 * cf0 + rs0;
            m1 = mn1; l1 = l1 * cf1 + rs1;
            #pragma unroll
            for (int nt = 0; nt < 8; ++nt) {
                oacc[nt][0] *= cf0; oacc[nt][1] *= cf0;
                oacc[nt][2] *= cf1; oacc[nt][3] *= cf1;
            }
        }
        __syncwarp();

        // ---- O += P V : 8 n-tiles (dh) x 16 k-steps (keys) ----
        const uint32_t* Pl0 = (const uint32_t*)&Ps[(wid * 16 + g) * PSTR];
        const uint32_t* Pl1 = (const uint32_t*)&Ps[(wid * 16 + g + 8) * PSTR];
        #pragma unroll
        for (int ks = 0; ks < 16; ++ks) {
            uint32_t af[4];
            af[0] = Pl0[ks * 8 + tg];
            af[1] = Pl1[ks * 8 + tg];
            af[2] = Pl0[ks * 8 + tg + 4];
            af[3] = Pl1[ks * 8 + tg + 4];
            #pragma unroll
            for (int nt = 0; nt < 8; ++nt) {
                const float* vp = Vb + (ks * 8 + tg) * KVSTR + nt * 8 + g;
                uint32_t bf[2];
                bf[0] = f2tf32(vp[0]);
                bf[1] = f2tf32(vp[4 * KVSTR]);
                mma_tf32(oacc[nt], af, bf);
            }
        }
    }

    // ---- epilogue ----
    const float inv0 = 1.0f / l0, inv1 = 1.0f / l1;
    float* op0 = ctx + qrow * D_M + h * DH;
    float* op1 = op0 + (size_t)8 * D_M;
    #pragma unroll
    for (int nt = 0; nt < 8; ++nt) {
        const int col = nt * 8 + tg * 2;
        *(float2*)(op0 + col) = make_float2(oacc[nt][0] * inv0, oacc[nt][1] * inv0);
        *(float2*)(op1 + col) = make_float2(oacc[nt][2] * inv1, oacc[nt][3] * inv1);
    }
}

// ---------------------------------------------------------------------------
// Launch
// ---------------------------------------------------------------------------
extern "C" void kernel_launch(void* const* d_in, const int* in_sizes, int n_in,
                              void* d_out, int out_size)
{
    (void)in_sizes; (void)n_in; (void)out_size;

    const float* query = (const float*)d_in[0];
    const int*   mask  = (const int*)  d_in[1];
    const float* Wq    = (const float*)d_in[2];
    const float* bq    = (const float*)d_in[3];
    const float* Wk    = (const float*)d_in[4];
    const float* bk    = (const float*)d_in[5];
    const float* Wv    = (const float*)d_in[6];
    const float* bv    = (const float*)d_in[7];
    const float* Wo    = (const float*)d_in[8];
    const float* bo    = (const float*)d_in[9];
    float* out = (float*)d_out;

    float *Qd, *Kd, *Vd, *Cd;
    cudaGetSymbolAddress((void**)&Qd, g_Q);
    cudaGetSymbolAddress((void**)&Kd, g_K);
    cudaGetSymbolAddress((void**)&Vd, g_V);
    cudaGetSymbolAddress((void**)&Cd, g_ctx);

    cudaFuncSetAttribute(sgemm_tf32_mma,
                         cudaFuncAttributeMaxDynamicSharedMemorySize,
                         GEMM_SMEM_BYTES);
    cudaFuncSetAttribute(flash_attn_mma,
                         cudaFuncAttributeMaxDynamicSharedMemorySize,
                         FA_SMEM_BYTES);

    dim3 gemm_grid(D_M / 128, MROWS / 128);  // (8, 64)

    sgemm_tf32_mma<<<gemm_grid, 256, GEMM_SMEM_BYTES>>>(query, Wq, bq, Qd);
    sgemm_tf32_mma<<<gemm_grid, 256, GEMM_SMEM_BYTES>>>(query, Wk, bk, Kd);
    sgemm_tf32_mma<<<gemm_grid, 256, GEMM_SMEM_BYTES>>>(query, Wv, bv, Vd);

    flash_attn_mma<<<dim3(T_S / 128, H_N, N_B), 256, FA_SMEM_BYTES>>>(
        Qd, Kd, Vd, mask, Cd);

    sgemm_tf32_mma<<<gemm_grid, 256, GEMM_SMEM_BYTES>>>(Cd, Wo, bo, out);
}

// round 8
// speedup vs baseline: 2.5281x; 1.0722x over previous
#include <cuda_runtime.h>
#include <math.h>
#include <stdint.h>

// Problem constants
#define N_B   4
#define T_S   2048
#define D_M   1024
#define H_N   16
#define DH    64
#define MROWS (N_B * T_S)   // 8192
#define GK    1024          // GEMM K

// ---------------------------------------------------------------------------
// Scratch (alloc-free rule: __device__ globals)
// ---------------------------------------------------------------------------
__device__ float g_Q  [(size_t)MROWS * D_M];
__device__ float g_K  [(size_t)MROWS * D_M];
__device__ float g_V  [(size_t)MROWS * D_M];
__device__ float g_ctx[(size_t)MROWS * D_M];

// ---------------------------------------------------------------------------
// Helpers (sm_100 plain target: NO tcgen05)
// ---------------------------------------------------------------------------
__device__ __forceinline__ uint32_t smem_to_u32(const void* p) {
    uint32_t a;
    asm("{ .reg .u64 t; cvta.to.shared.u64 t, %1; cvt.u32.u64 %0, t; }"
        : "=r"(a) : "l"(p));
    return a;
}
__device__ __forceinline__ void cpa16(uint32_t dst, const void* src) {
    asm volatile("cp.async.cg.shared.global [%0], [%1], 16;"
                 :: "r"(dst), "l"(src) : "memory");
}
#define CP_COMMIT() asm volatile("cp.async.commit_group;" ::: "memory")

__device__ __forceinline__ uint32_t f2tf32(float x) {
    uint32_t y;
    asm("cvt.rna.tf32.f32 %0, %1;" : "=r"(y) : "f"(x));
    return y;
}
// D(16x8,f32) += A(16x8,tf32 row) * B(8x8,tf32 col)
__device__ __forceinline__ void mma_tf32(float* d, const uint32_t* a,
                                         const uint32_t* b) {
    asm volatile(
        "mma.sync.aligned.m16n8k8.row.col.f32.tf32.tf32.f32 "
        "{%0,%1,%2,%3}, {%4,%5,%6,%7}, {%8,%9}, {%0,%1,%2,%3};"
        : "+f"(d[0]), "+f"(d[1]), "+f"(d[2]), "+f"(d[3])
        : "r"(a[0]), "r"(a[1]), "r"(a[2]), "r"(a[3]),
          "r"(b[0]), "r"(b[1]));
}

// ---------------------------------------------------------------------------
// TF32 tensor-core SGEMM (validated R6/R7): C = A @ B^T + bias
// ---------------------------------------------------------------------------
#define TSTR 36
#define TILE_FLOATS (128 * TSTR)
#define A_BYTES (TILE_FLOATS * 4)
#define GEMM_SMEM_BYTES (4 * A_BYTES)

__global__ __launch_bounds__(256, 2)
void sgemm_tf32_mma(const float* __restrict__ A, const float* __restrict__ B,
                    const float* __restrict__ bias, float* __restrict__ C)
{
    extern __shared__ float sm[];
    const uint32_t sb = smem_to_u32(sm);
    const int tid  = threadIdx.x;
    const int wid  = tid >> 5;
    const int lane = tid & 31;
    const int g    = lane >> 2;
    const int tg   = lane & 3;
    const int warp_m = wid & 1;
    const int warp_n = wid >> 1;
    const int m0 = blockIdx.y * 128;
    const int n0 = blockIdx.x * 128;

    const int lr  = tid >> 3;
    const int lc4 = (tid & 7) * 4;
    const uint32_t st_off = (uint32_t)((lr * TSTR + lc4) * 4);
    const float* Ag = A + (size_t)(m0 + lr) * GK + lc4;
    const float* Bg = B + (size_t)(n0 + lr) * GK + lc4;

    #pragma unroll
    for (int i = 0; i < 4; ++i) {
        cpa16(sb + st_off + i * (32 * TSTR * 4), Ag + (size_t)(32 * i) * GK);
        cpa16(sb + 2 * A_BYTES + st_off + i * (32 * TSTR * 4),
              Bg + (size_t)(32 * i) * GK);
    }
    CP_COMMIT();

    float acc[4][4][4];
    #pragma unroll
    for (int mt = 0; mt < 4; ++mt)
        #pragma unroll
        for (int nt = 0; nt < 4; ++nt)
            #pragma unroll
            for (int u = 0; u < 4; ++u) acc[mt][nt][u] = 0.0f;

    const int NT = GK / 32;
    for (int kt = 0; kt < NT; ++kt) {
        const int buf = kt & 1;
        if (kt + 1 < NT) {
            const int nb = buf ^ 1;
            const float* Ag2 = Ag + (kt + 1) * 32;
            const float* Bg2 = Bg + (kt + 1) * 32;
            #pragma unroll
            for (int i = 0; i < 4; ++i) {
                cpa16(sb + nb * A_BYTES + st_off + i * (32 * TSTR * 4),
                      Ag2 + (size_t)(32 * i) * GK);
                cpa16(sb + 2 * A_BYTES + nb * A_BYTES + st_off + i * (32 * TSTR * 4),
                      Bg2 + (size_t)(32 * i) * GK);
            }
            CP_COMMIT();
            asm volatile("cp.async.wait_group 1;" ::: "memory");
        } else {
            asm volatile("cp.async.wait_group 0;" ::: "memory");
        }
        __syncthreads();

        const float* Asb = sm + buf * TILE_FLOATS;
        const float* Bsb = sm + 2 * TILE_FLOATS + buf * TILE_FLOATS;

        #pragma unroll
        for (int ks = 0; ks < 4; ++ks) {
            const int kc = ks * 8 + tg;
            uint32_t af[4][4], bf[4][2];
            #pragma unroll
            for (int mt = 0; mt < 4; ++mt) {
                const float* p = Asb + (warp_m * 64 + mt * 16 + g) * TSTR + kc;
                af[mt][0] = f2tf32(p[0]);
                af[mt][1] = f2tf32(p[8 * TSTR]);
                af[mt][2] = f2tf32(p[4]);
                af[mt][3] = f2tf32(p[8 * TSTR + 4]);
            }
            #pragma unroll
            for (int nt = 0; nt < 4; ++nt) {
                const float* p = Bsb + (warp_n * 32 + nt * 8 + g) * TSTR + kc;
                bf[nt][0] = f2tf32(p[0]);
                bf[nt][1] = f2tf32(p[4]);
            }
            #pragma unroll
            for (int mt = 0; mt < 4; ++mt)
                #pragma unroll
                for (int nt = 0; nt < 4; ++nt)
                    mma_tf32(acc[mt][nt], af[mt], bf[nt]);
        }
        __syncthreads();
    }

    #pragma unroll
    for (int nt = 0; nt < 4; ++nt) {
        const int col = n0 + warp_n * 32 + nt * 8 + tg * 2;
        const float b0 = bias[col], b1 = bias[col + 1];
        #pragma unroll
        for (int mt = 0; mt < 4; ++mt) {
            const int row = m0 + warp_m * 64 + mt * 16 + g;
            float2 v0 = make_float2(acc[mt][nt][0] + b0, acc[mt][nt][1] + b1);
            float2 v1 = make_float2(acc[mt][nt][2] + b0, acc[mt][nt][3] + b1);
            *(float2*)(C + (size_t)row * D_M + col)       = v0;
            *(float2*)(C + (size_t)(row + 8) * D_M + col) = v1;
        }
    }
}

// ---------------------------------------------------------------------------
// Flash attention on mma.sync tf32 — R8:
//  * 64-key s-tiles, double-buffered K/V => smem 104 KB => 2 CTAs/SM.
//  * K/V pre-converted to tf32 IN SMEM once per tile (kills the 8x-redundant
//    per-warp CVT stream; numerically identical to converting at each read).
//  * Warp-local softmax; P staged pre-converted (warp-private rows).
// ---------------------------------------------------------------------------
#define SK    64                          // keys per s-tile
#define KVSTR 68                          // floats per K/V smem row
#define KVT   (SK * KVSTR)                // 4352 floats per tile
#define OFF_V (2 * KVT)
#define OFF_P (4 * KVT)
#define PSTR  68
#define FA_SMEM_FLOATS (4 * KVT + 128 * PSTR)   // 26112
#define FA_SMEM_BYTES  (FA_SMEM_FLOATS * 4)     // 104448

__global__ __launch_bounds__(256, 2)
void flash_attn_mma(const float* __restrict__ Q, const float* __restrict__ K,
                    const float* __restrict__ V, const int* __restrict__ mask,
                    float* __restrict__ ctx)
{
    extern __shared__ float sm[];
    const uint32_t sb = smem_to_u32(sm);
    float* Ps = sm + OFF_P;

    const int tid  = threadIdx.x;
    const int wid  = tid >> 5;
    const int lane = tid & 31;
    const int g    = lane >> 2;
    const int tg   = lane & 3;
    const int t0 = blockIdx.x * 128;
    const int h  = blockIdx.y;
    const int n  = blockIdx.z;

    // ---- Q fragments: rows (16w+g, 16w+g+8), once per block ----
    const size_t qrow = (size_t)(n * T_S + t0 + wid * 16 + g);
    const float* Qp0 = Q + qrow * D_M + h * DH;
    const float* Qp1 = Qp0 + (size_t)8 * D_M;
    uint32_t qf[8][4];
    #pragma unroll
    for (int ks = 0; ks < 8; ++ks) {
        qf[ks][0] = f2tf32(Qp0[ks * 8 + tg]);
        qf[ks][1] = f2tf32(Qp1[ks * 8 + tg]);
        qf[ks][2] = f2tf32(Qp0[ks * 8 + tg + 4]);
        qf[ks][3] = f2tf32(Qp1[ks * 8 + tg + 4]);
    }

    const float rsc0 = (mask[n * T_S + t0 + wid * 16 + g]     != 0) ? 0.125f : 0.0f;
    const float rsc1 = (mask[n * T_S + t0 + wid * 16 + g + 8] != 0) ? 0.125f : 0.0f;

    float m0 = -1e30f, l0 = 0.0f, m1 = -1e30f, l1 = 0.0f;
    float oacc[8][4];
    #pragma unroll
    for (int nt = 0; nt < 8; ++nt)
        #pragma unroll
        for (int u = 0; u < 4; ++u) oacc[nt][u] = 0.0f;

    // ---- cp.async mapping: thread -> K/V row tid>>2, 16-col quarter tid&3 ----
    const int cr = tid >> 2;              // 0..63
    const int cq = (tid & 3) * 16;        // 0,16,32,48
    const float* Kg = K + ((size_t)(n * T_S) + cr) * D_M + h * DH + cq;
    const float* Vg = V + ((size_t)(n * T_S) + cr) * D_M + h * DH + cq;
    const uint32_t cdst = (uint32_t)((cr * KVSTR + cq) * 4);

    // prologue: tile 0 -> buffer 0
    #pragma unroll
    for (int j = 0; j < 4; ++j) {
        cpa16(sb + cdst + j * 16,             Kg + j * 4);
        cpa16(sb + OFF_V * 4 + cdst + j * 16, Vg + j * 4);
    }
    CP_COMMIT();

    const int NST = T_S / SK;   // 32
    for (int st = 0; st < NST; ++st) {
        const int buf = st & 1;
        asm volatile("cp.async.wait_group 0;" ::: "memory");
        __syncthreads();

        if (st + 1 < NST) {
            const int nb = buf ^ 1;
            const size_t go = (size_t)(st + 1) * SK * D_M;
            #pragma unroll
            for (int j = 0; j < 4; ++j) {
                cpa16(sb + nb * KVT * 4 + cdst + j * 16,           Kg + go + j * 4);
                cpa16(sb + (OFF_V + nb * KVT) * 4 + cdst + j * 16, Vg + go + j * 4);
            }
            CP_COMMIT();
        }

        // ---- pre-convert K and V tiles to tf32 in place (once per tile) ----
        float* Kb = sm + buf * KVT;
        float* Vb = sm + OFF_V + buf * KVT;
        #pragma unroll
        for (int i = 0; i < 4; ++i) {
            const int idx4 = tid + i * 256;          // 0..1023 float4s
            const int r = idx4 >> 4, c4 = (idx4 & 15) * 4;
            float4 kv = *(float4*)&Kb[r * KVSTR + c4];
            *(uint4*)&Kb[r * KVSTR + c4] =
                make_uint4(f2tf32(kv.x), f2tf32(kv.y), f2tf32(kv.z), f2tf32(kv.w));
            float4 vv = *(float4*)&Vb[r * KVSTR + c4];
            *(uint4*)&Vb[r * KVSTR + c4] =
                make_uint4(f2tf32(vv.x), f2tf32(vv.y), f2tf32(vv.z), f2tf32(vv.w));
        }
        __syncthreads();

        const uint32_t* Kb32 = (const uint32_t*)Kb;
        const uint32_t* Vb32 = (const uint32_t*)Vb;

        // ---- S = Q K^T : 8 n-tiles x 8 k-steps ----
        float sacc[8][4];
        #pragma unroll
        for (int nt = 0; nt < 8; ++nt)
            #pragma unroll
            for (int u = 0; u < 4; ++u) sacc[nt][u] = 0.0f;

        #pragma unroll
        for (int ks = 0; ks < 8; ++ks) {
            #pragma unroll
            for (int nt = 0; nt < 8; ++nt) {
                const uint32_t* kp = Kb32 + (nt * 8 + g) * KVSTR + ks * 8 + tg;
                uint32_t bf[2];
                bf[0] = kp[0];
                bf[1] = kp[4];
                mma_tf32(sacc[nt], qf[ks], bf);
            }
        }

        // ---- online softmax (rows g, g+8; reduce over tg lanes) ----
        {
            float mx0 = -1e30f, mx1 = -1e30f;
            #pragma unroll
            for (int nt = 0; nt < 8; ++nt) {
                sacc[nt][0] *= rsc0; sacc[nt][1] *= rsc0;
                sacc[nt][2] *= rsc1; sacc[nt][3] *= rsc1;
                mx0 = fmaxf(mx0, fmaxf(sacc[nt][0], sacc[nt][1]));
                mx1 = fmaxf(mx1, fmaxf(sacc[nt][2], sacc[nt][3]));
            }
            mx0 = fmaxf(mx0, __shfl_xor_sync(0xffffffffu, mx0, 1));
            mx0 = fmaxf(mx0, __shfl_xor_sync(0xffffffffu, mx0, 2));
            mx1 = fmaxf(mx1, __shfl_xor_sync(0xffffffffu, mx1, 1));
            mx1 = fmaxf(mx1, __shfl_xor_sync(0xffffffffu, mx1, 2));

            const float mn0 = fmaxf(m0, mx0), mn1 = fmaxf(m1, mx1);
            const float cf0 = __expf(m0 - mn0), cf1 = __expf(m1 - mn1);
            float rs0 = 0.0f, rs1 = 0.0f;

            uint32_t* Pr0 = (uint32_t*)&Ps[(wid * 16 + g) * PSTR + tg * 2];
            uint32_t* Pr1 = (uint32_t*)&Ps[(wid * 16 + g + 8) * PSTR + tg * 2];
            #pragma unroll
            for (int nt = 0; nt < 8; ++nt) {
                float p0 = __expf(sacc[nt][0] - mn0);
                float p1 = __expf(sacc[nt][1] - mn0);
                float p2 = __expf(sacc[nt][2] - mn1);
                float p3 = __expf(sacc[nt][3] - mn1);
                rs0 += p0 + p1;
                rs1 += p2 + p3;
                *(uint2*)(Pr0 + nt * 8) = make_uint2(f2tf32(p0), f2tf32(p1));
                *(uint2*)(Pr1 + nt * 8) = make_uint2(f2tf32(p2), f2tf32(p3));
            }
            rs0 += __shfl_xor_sync(0xffffffffu, rs0, 1);
            rs0 += __shfl_xor_sync(0xffffffffu, rs0, 2);
            rs1 += __shfl_xor_sync(0xffffffffu, rs1, 1);
            rs1 += __shfl_xor_sync(0xffffffffu, rs1, 2);

            m0 = mn0; l0 = l0 * cf0 + rs0;
            m1 = mn1; l1 = l1 * cf1 + rs1;
            #pragma unroll
            for (int nt = 0; nt < 8; ++nt) {
                oacc[nt][0] *= cf0; oacc[nt][1] *= cf0;
                oacc[nt][2] *= cf1; oacc[nt][3] *= cf1;
            }
        }
        __syncwarp();

        // ---- O += P V : 8 k-steps (keys) x 8 n-tiles (dh) ----
        const uint32_t* Pl0 = (const uint32_t*)&Ps[(wid * 16 + g) * PSTR];
        const uint32_t* Pl1 = (const uint32_t*)&Ps[(wid * 16 + g + 8) * PSTR];
        #pragma unroll
        for (int ks = 0; ks < 8; ++ks) {
            uint32_t af[4];
            af[0] = Pl0[ks * 8 + tg];
            af[1] = Pl1[ks * 8 + tg];
            af[2] = Pl0[ks * 8 + tg + 4];
            af[3] = Pl1[ks * 8 + tg + 4];
            #pragma unroll
            for (int nt = 0; nt < 8; ++nt) {
                const uint32_t* vp = Vb32 + (ks * 8 + tg) * KVSTR + nt * 8 + g;
                uint32_t bf[2];
                bf[0] = vp[0];
                bf[1] = vp[4 * KVSTR];
                mma_tf32(oacc[nt], af, bf);
            }
        }
    }

    // ---- epilogue ----
    const float inv0 = 1.0f / l0, inv1 = 1.0f / l1;
    float* op0 = ctx + qrow * D_M + h * DH;
    float* op1 = op0 + (size_t)8 * D_M;
    #pragma unroll
    for (int nt = 0; nt < 8; ++nt) {
        const int col = nt * 8 + tg * 2;
        *(float2*)(op0 + col) = make_float2(oacc[nt][0] * inv0, oacc[nt][1] * inv0);
        *(float2*)(op1 + col) = make_float2(oacc[nt][2] * inv1, oacc[nt][3] * inv1);
    }
}

// ---------------------------------------------------------------------------
// Launch
// ---------------------------------------------------------------------------
extern "C" void kernel_launch(void* const* d_in, const int* in_sizes, int n_in,
                              void* d_out, int out_size)
{
    (void)in_sizes; (void)n_in; (void)out_size;

    const float* query = (const float*)d_in[0];
    const int*   mask  = (const int*)  d_in[1];
    const float* Wq    = (const float*)d_in[2];
    const float* bq    = (const float*)d_in[3];
    const float* Wk    = (const float*)d_in[4];
    const float* bk    = (const float*)d_in[5];
    const float* Wv    = (const float*)d_in[6];
    const float* bv    = (const float*)d_in[7];
    const float* Wo    = (const float*)d_in[8];
    const float* bo    = (const float*)d_in[9];
    float* out = (float*)d_out;

    float *Qd, *Kd, *Vd, *Cd;
    cudaGetSymbolAddress((void**)&Qd, g_Q);
    cudaGetSymbolAddress((void**)&Kd, g_K);
    cudaGetSymbolAddress((void**)&Vd, g_V);
    cudaGetSymbolAddress((void**)&Cd, g_ctx);

    cudaFuncSetAttribute(sgemm_tf32_mma,
                         cudaFuncAttributeMaxDynamicSharedMemorySize,
                         GEMM_SMEM_BYTES);
    cudaFuncSetAttribute(flash_attn_mma,
                         cudaFuncAttributeMaxDynamicSharedMemorySize,
                         FA_SMEM_BYTES);

    dim3 gemm_grid(D_M / 128, MROWS / 128);  // (8, 64)

    sgemm_tf32_mma<<<gemm_grid, 256, GEMM_SMEM_BYTES>>>(query, Wq, bq, Qd);
    sgemm_tf32_mma<<<gemm_grid, 256, GEMM_SMEM_BYTES>>>(query, Wk, bk, Kd);
    sgemm_tf32_mma<<<gemm_grid, 256, GEMM_SMEM_BYTES>>>(query, Wv, bv, Vd);

    flash_attn_mma<<<dim3(T_S / 128, H_N, N_B), 256, FA_SMEM_BYTES>>>(
        Qd, Kd, Vd, mask, Cd);

    sgemm_tf32_mma<<<gemm_grid, 256, GEMM_SMEM_BYTES>>>(Cd, Wo, bo, out);
}

// round 9
// speedup vs baseline: 3.4760x; 1.3750x over previous
#include <cuda_runtime.h>
#include <cuda_fp16.h>
#include <math.h>
#include <stdint.h>

// Problem constants
#define N_B   4
#define T_S   2048
#define D_M   1024
#define H_N   16
#define DH    64
#define MROWS (N_B * T_S)   // 8192
#define GK    1024          // GEMM K

// ---------------------------------------------------------------------------
// Scratch (alloc-free rule: __device__ globals)
// ---------------------------------------------------------------------------
__device__ float g_Q  [(size_t)MROWS * D_M];
__device__ float g_K  [(size_t)MROWS * D_M];
__device__ float g_V  [(size_t)MROWS * D_M];
__device__ float g_ctx[(size_t)MROWS * D_M];

// ---------------------------------------------------------------------------
// Helpers (sm_100 plain target: NO tcgen05)
// ---------------------------------------------------------------------------
__device__ __forceinline__ uint32_t smem_to_u32(const void* p) {
    uint32_t a;
    asm("{ .reg .u64 t; cvta.to.shared.u64 t, %1; cvt.u32.u64 %0, t; }"
        : "=r"(a) : "l"(p));
    return a;
}
__device__ __forceinline__ void cpa16(uint32_t dst, const void* src) {
    asm volatile("cp.async.cg.shared.global [%0], [%1], 16;"
                 :: "r"(dst), "l"(src) : "memory");
}
#define CP_COMMIT() asm volatile("cp.async.commit_group;" ::: "memory")

__device__ __forceinline__ uint32_t f2tf32(float x) {
    uint32_t y;
    asm("cvt.rna.tf32.f32 %0, %1;" : "=r"(y) : "f"(x));
    return y;
}
__device__ __forceinline__ uint32_t packh2(float lo, float hi) {
    __half2 h = __floats2half2_rn(lo, hi);
    return *(uint32_t*)&h;
}
// D(16x8,f32) += A(16x8,tf32 row) * B(8x8,tf32 col)
__device__ __forceinline__ void mma_tf32(float* d, const uint32_t* a,
                                         const uint32_t* b) {
    asm volatile(
        "mma.sync.aligned.m16n8k8.row.col.f32.tf32.tf32.f32 "
        "{%0,%1,%2,%3}, {%4,%5,%6,%7}, {%8,%9}, {%0,%1,%2,%3};"
        : "+f"(d[0]), "+f"(d[1]), "+f"(d[2]), "+f"(d[3])
        : "r"(a[0]), "r"(a[1]), "r"(a[2]), "r"(a[3]),
          "r"(b[0]), "r"(b[1]));
}
// D(16x8,f32) += A(16x16,f16 row) * B(16x8,f16 col)
__device__ __forceinline__ void mma_f16(float* d, const uint32_t* a,
                                        uint32_t b0, uint32_t b1) {
    asm volatile(
        "mma.sync.aligned.m16n8k16.row.col.f32.f16.f16.f32 "
        "{%0,%1,%2,%3}, {%4,%5,%6,%7}, {%8,%9}, {%0,%1,%2,%3};"
        : "+f"(d[0]), "+f"(d[1]), "+f"(d[2]), "+f"(d[3])
        : "r"(a[0]), "r"(a[1]), "r"(a[2]), "r"(a[3]),
          "r"(b0), "r"(b1));
}
__device__ __forceinline__ void ldsm_x2(uint32_t addr, uint32_t& r0, uint32_t& r1) {
    asm volatile("ldmatrix.sync.aligned.m8n8.x2.shared.b16 {%0,%1}, [%2];"
                 : "=r"(r0), "=r"(r1) : "r"(addr));
}
__device__ __forceinline__ void ldsm_x2t(uint32_t addr, uint32_t& r0, uint32_t& r1) {
    asm volatile("ldmatrix.sync.aligned.m8n8.x2.trans.shared.b16 {%0,%1}, [%2];"
                 : "=r"(r0), "=r"(r1) : "r"(addr));
}
__device__ __forceinline__ void ldsm_x4(uint32_t addr, uint32_t* r) {
    asm volatile("ldmatrix.sync.aligned.m8n8.x4.shared.b16 {%0,%1,%2,%3}, [%4];"
                 : "=r"(r[0]), "=r"(r[1]), "=r"(r[2]), "=r"(r[3]) : "r"(addr));
}

// ---------------------------------------------------------------------------
// TF32 tensor-core SGEMM (validated R6-R8): C = A @ B^T + bias
// ---------------------------------------------------------------------------
#define TSTR 36
#define TILE_FLOATS (128 * TSTR)
#define A_BYTES (TILE_FLOATS * 4)
#define GEMM_SMEM_BYTES (4 * A_BYTES)

__global__ __launch_bounds__(256, 2)
void sgemm_tf32_mma(const float* __restrict__ A, const float* __restrict__ B,
                    const float* __restrict__ bias, float* __restrict__ C)
{
    extern __shared__ float sm[];
    const uint32_t sb = smem_to_u32(sm);
    const int tid  = threadIdx.x;
    const int wid  = tid >> 5;
    const int lane = tid & 31;
    const int g    = lane >> 2;
    const int tg   = lane & 3;
    const int warp_m = wid & 1;
    const int warp_n = wid >> 1;
    const int m0 = blockIdx.y * 128;
    const int n0 = blockIdx.x * 128;

    const int lr  = tid >> 3;
    const int lc4 = (tid & 7) * 4;
    const uint32_t st_off = (uint32_t)((lr * TSTR + lc4) * 4);
    const float* Ag = A + (size_t)(m0 + lr) * GK + lc4;
    const float* Bg = B + (size_t)(n0 + lr) * GK + lc4;

    #pragma unroll
    for (int i = 0; i < 4; ++i) {
        cpa16(sb + st_off + i * (32 * TSTR * 4), Ag + (size_t)(32 * i) * GK);
        cpa16(sb + 2 * A_BYTES + st_off + i * (32 * TSTR * 4),
              Bg + (size_t)(32 * i) * GK);
    }
    CP_COMMIT();

    float acc[4][4][4];
    #pragma unroll
    for (int mt = 0; mt < 4; ++mt)
        #pragma unroll
        for (int nt = 0; nt < 4; ++nt)
            #pragma unroll
            for (int u = 0; u < 4; ++u) acc[mt][nt][u] = 0.0f;

    const int NT = GK / 32;
    for (int kt = 0; kt < NT; ++kt) {
        const int buf = kt & 1;
        if (kt + 1 < NT) {
            const int nb = buf ^ 1;
            const float* Ag2 = Ag + (kt + 1) * 32;
            const float* Bg2 = Bg + (kt + 1) * 32;
            #pragma unroll
            for (int i = 0; i < 4; ++i) {
                cpa16(sb + nb * A_BYTES + st_off + i * (32 * TSTR * 4),
                      Ag2 + (size_t)(32 * i) * GK);
                cpa16(sb + 2 * A_BYTES + nb * A_BYTES + st_off + i * (32 * TSTR * 4),
                      Bg2 + (size_t)(32 * i) * GK);
            }
            CP_COMMIT();
            asm volatile("cp.async.wait_group 1;" ::: "memory");
        } else {
            asm volatile("cp.async.wait_group 0;" ::: "memory");
        }
        __syncthreads();

        const float* Asb = sm + buf * TILE_FLOATS;
        const float* Bsb = sm + 2 * TILE_FLOATS + buf * TILE_FLOATS;

        #pragma unroll
        for (int ks = 0; ks < 4; ++ks) {
            const int kc = ks * 8 + tg;
            uint32_t af[4][4], bf[4][2];
            #pragma unroll
            for (int mt = 0; mt < 4; ++mt) {
                const float* p = Asb + (warp_m * 64 + mt * 16 + g) * TSTR + kc;
                af[mt][0] = f2tf32(p[0]);
                af[mt][1] = f2tf32(p[8 * TSTR]);
                af[mt][2] = f2tf32(p[4]);
                af[mt][3] = f2tf32(p[8 * TSTR + 4]);
            }
            #pragma unroll
            for (int nt = 0; nt < 4; ++nt) {
                const float* p = Bsb + (warp_n * 32 + nt * 8 + g) * TSTR + kc;
                bf[nt][0] = f2tf32(p[0]);
                bf[nt][1] = f2tf32(p[4]);
            }
            #pragma unroll
            for (int mt = 0; mt < 4; ++mt)
                #pragma unroll
                for (int nt = 0; nt < 4; ++nt)
                    mma_tf32(acc[mt][nt], af[mt], bf[nt]);
        }
        __syncthreads();
    }

    #pragma unroll
    for (int nt = 0; nt < 4; ++nt) {
        const int col = n0 + warp_n * 32 + nt * 8 + tg * 2;
        const float b0 = bias[col], b1 = bias[col + 1];
        #pragma unroll
        for (int mt = 0; mt < 4; ++mt) {
            const int row = m0 + warp_m * 64 + mt * 16 + g;
            float2 v0 = make_float2(acc[mt][nt][0] + b0, acc[mt][nt][1] + b1);
            float2 v1 = make_float2(acc[mt][nt][2] + b0, acc[mt][nt][3] + b1);
            *(float2*)(C + (size_t)row * D_M + col)       = v0;
            *(float2*)(C + (size_t)(row + 8) * D_M + col) = v1;
        }
    }
}

// ---------------------------------------------------------------------------
// Flash attention — R9: fp16 operands (same 10-bit mantissa as tf32, fp32
// accum), m16n8k16 MMA (half the MMA count), f16 smem tiles (half the LDS
// bytes), ldmatrix fragment loads (V via .trans from natural [key][dh]).
// K/V: gmem(L2) -> regs -> cvt f16 -> smem, double buffered.
// ---------------------------------------------------------------------------
#define SK    64                      // keys per s-tile
#define KSTRH 72                      // halves per K/V smem row (144 B)
#define KVTB  (SK * KSTRH * 2)        // 9216 B per tile
#define OFF_VH (2 * KVTB)             // V region after double K
#define OFF_PH (4 * KVTB)             // P region after double V
#define FA_SMEM_BYTES (4 * KVTB + 128 * KSTRH * 2)  // 55296

__global__ __launch_bounds__(256, 2)
void flash_attn_f16(const float* __restrict__ Q, const float* __restrict__ K,
                    const float* __restrict__ V, const int* __restrict__ mask,
                    float* __restrict__ ctx)
{
    extern __shared__ char smc[];
    const uint32_t sb = smem_to_u32(smc);

    const int tid  = threadIdx.x;
    const int wid  = tid >> 5;
    const int lane = tid & 31;
    const int g    = lane >> 2;
    const int tg   = lane & 3;
    const int t0 = blockIdx.x * 128;
    const int h  = blockIdx.y;
    const int n  = blockIdx.z;

    // ---- Q fragments (f16 pairs), rows (16w+g, 16w+g+8), once ----
    const size_t qrow = (size_t)(n * T_S + t0 + wid * 16 + g);
    const float* Qp0 = Q + qrow * D_M + h * DH;
    const float* Qp1 = Qp0 + (size_t)8 * D_M;
    uint32_t qf[4][4];
    #pragma unroll
    for (int ks = 0; ks < 4; ++ks) {
        const int c = ks * 16 + 2 * tg;
        qf[ks][0] = packh2(Qp0[c],     Qp0[c + 1]);
        qf[ks][1] = packh2(Qp1[c],     Qp1[c + 1]);
        qf[ks][2] = packh2(Qp0[c + 8], Qp0[c + 9]);
        qf[ks][3] = packh2(Qp1[c + 8], Qp1[c + 9]);
    }

    const float rsc0 = (mask[n * T_S + t0 + wid * 16 + g]     != 0) ? 0.125f : 0.0f;
    const float rsc1 = (mask[n * T_S + t0 + wid * 16 + g + 8] != 0) ? 0.125f : 0.0f;

    float m0 = -1e30f, l0 = 0.0f, m1 = -1e30f, l1 = 0.0f;
    float oacc[8][4];
    #pragma unroll
    for (int nt = 0; nt < 8; ++nt)
        #pragma unroll
        for (int u = 0; u < 4; ++u) oacc[nt][u] = 0.0f;

    // ---- converter mapping: thread -> (key row cr, 16-dh quarter cq) ----
    const int cr = tid >> 2;
    const int cq = (tid & 3) * 16;
    const float* Kg = K + ((size_t)(n * T_S) + cr) * D_M + h * DH + cq;
    const float* Vg = V + ((size_t)(n * T_S) + cr) * D_M + h * DH + cq;
    const uint32_t cdst = (uint32_t)(cr * (KSTRH * 2) + cq * 2);  // bytes in tile

    // ---- ldmatrix per-lane offsets (bytes) ----
    const uint32_t koff = (uint32_t)(((lane & 7) * KSTRH + ((lane >> 3) & 1) * 8) * 2);
    const uint32_t voff = (uint32_t)((lane & 15) * KSTRH * 2);
    const uint32_t poff = (uint32_t)((lane & 15) * KSTRH * 2 + ((lane >> 4) & 1) * 16);
    const uint32_t PhB  = sb + OFF_PH + wid * 16 * (KSTRH * 2);

    float4 kst[4], vst[4];
    // prologue: tile 0 -> regs -> f16 buf 0
    #pragma unroll
    for (int j = 0; j < 4; ++j) { kst[j] = *(const float4*)(Kg + j * 4);
                                  vst[j] = *(const float4*)(Vg + j * 4); }
    {
        char* kd = smc + cdst;
        char* vd = smc + OFF_VH + cdst;
        #pragma unroll
        for (int j = 0; j < 4; ++j) {
            *(uint2*)(kd + j * 8) = make_uint2(packh2(kst[j].x, kst[j].y),
                                               packh2(kst[j].z, kst[j].w));
            *(uint2*)(vd + j * 8) = make_uint2(packh2(vst[j].x, vst[j].y),
                                               packh2(vst[j].z, vst[j].w));
        }
    }

    const int NST = T_S / SK;   // 32
    for (int st = 0; st < NST; ++st) {
        const int buf = st & 1;
        const int nxt = (st + 1 < NST);
        const size_t go = (size_t)(st + 1) * SK * D_M;

        if (nxt) {   // stage next K early (L2 latency hidden by S-phase)
            #pragma unroll
            for (int j = 0; j < 4; ++j) kst[j] = *(const float4*)(Kg + go + j * 4);
        }
        __syncthreads();   // f16 buf[buf] ready for all warps

        const uint32_t KhB = sb + buf * KVTB;
        const uint32_t VhB = sb + OFF_VH + buf * KVTB;

        // ---- S = Q K^T : 4 k16-steps x 8 n-tiles ----
        float sacc[8][4];
        #pragma unroll
        for (int nt = 0; nt < 8; ++nt)
            #pragma unroll
            for (int u = 0; u < 4; ++u) sacc[nt][u] = 0.0f;

        #pragma unroll
        for (int ks = 0; ks < 4; ++ks) {
            #pragma unroll
            for (int nt = 0; nt < 8; ++nt) {
                uint32_t b0, b1;
                ldsm_x2(KhB + (uint32_t)((nt * 8 * KSTRH + ks * 16) * 2) + koff, b0, b1);
                mma_f16(sacc[nt], qf[ks], b0, b1);
            }
        }

        if (nxt) {   // stage next V (hidden by softmax + PV)
            #pragma unroll
            for (int j = 0; j < 4; ++j) vst[j] = *(const float4*)(Vg + go + j * 4);
        }

        // ---- online softmax (rows g, g+8; reduce over tg lanes) ----
        {
            float mx0 = -1e30f, mx1 = -1e30f;
            #pragma unroll
            for (int nt = 0; nt < 8; ++nt) {
                sacc[nt][0] *= rsc0; sacc[nt][1] *= rsc0;
                sacc[nt][2] *= rsc1; sacc[nt][3] *= rsc1;
                mx0 = fmaxf(mx0, fmaxf(sacc[nt][0], sacc[nt][1]));
                mx1 = fmaxf(mx1, fmaxf(sacc[nt][2], sacc[nt][3]));
            }
            mx0 = fmaxf(mx0, __shfl_xor_sync(0xffffffffu, mx0, 1));
            mx0 = fmaxf(mx0, __shfl_xor_sync(0xffffffffu, mx0, 2));
            mx1 = fmaxf(mx1, __shfl_xor_sync(0xffffffffu, mx1, 1));
            mx1 = fmaxf(mx1, __shfl_xor_sync(0xffffffffu, mx1, 2));

            const float mn0 = fmaxf(m0, mx0), mn1 = fmaxf(m1, mx1);
            const float cf0 = __expf(m0 - mn0), cf1 = __expf(m1 - mn1);
            float rs0 = 0.0f, rs1 = 0.0f;

            char* Pr0 = smc + OFF_PH + (wid * 16 + g)     * (KSTRH * 2) + tg * 4;
            char* Pr1 = smc + OFF_PH + (wid * 16 + g + 8) * (KSTRH * 2) + tg * 4;
            #pragma unroll
            for (int nt = 0; nt < 8; ++nt) {
                float p0 = __expf(sacc[nt][0] - mn0);
                float p1 = __expf(sacc[nt][1] - mn0);
                float p2 = __expf(sacc[nt][2] - mn1);
                float p3 = __expf(sacc[nt][3] - mn1);
                rs0 += p0 + p1;
                rs1 += p2 + p3;
                *(uint32_t*)(Pr0 + nt * 16) = packh2(p0, p1);
                *(uint32_t*)(Pr1 + nt * 16) = packh2(p2, p3);
            }
            rs0 += __shfl_xor_sync(0xffffffffu, rs0, 1);
            rs0 += __shfl_xor_sync(0xffffffffu, rs0, 2);
            rs1 += __shfl_xor_sync(0xffffffffu, rs1, 1);
            rs1 += __shfl_xor_sync(0xffffffffu, rs1, 2);

            m0 = mn0; l0 = l0 * cf0 + rs0;
            m1 = mn1; l1 = l1 * cf1 + rs1;
            #pragma unroll
            for (int nt = 0; nt < 8; ++nt) {
                oacc[nt][0] *= cf0; oacc[nt][1] *= cf0;
                oacc[nt][2] *= cf1; oacc[nt][3] *= cf1;
            }
        }
        __syncwarp();

        if (nxt) {   // convert + store next K into buf^1 (consumed, safe)
            char* kd = smc + (buf ^ 1) * KVTB + cdst;
            #pragma unroll
            for (int j = 0; j < 4; ++j)
                *(uint2*)(kd + j * 8) = make_uint2(packh2(kst[j].x, kst[j].y),
                                                   packh2(kst[j].z, kst[j].w));
        }

        // ---- O += P V : 4 k16-steps (keys) x 8 n-tiles (dh) ----
        #pragma unroll
        for (int ks = 0; ks < 4; ++ks) {
            uint32_t af[4];
            ldsm_x4(PhB + ks * 32 + poff, af);
            #pragma unroll
            for (int nt = 0; nt < 8; ++nt) {
                uint32_t b0, b1;
                ldsm_x2t(VhB + (uint32_t)((ks * 16 * KSTRH + nt * 8) * 2) + voff, b0, b1);
                mma_f16(oacc[nt], af, b0, b1);
            }
        }

        if (nxt) {   // convert + store next V into buf^1
            char* vd = smc + OFF_VH + (buf ^ 1) * KVTB + cdst;
            #pragma unroll
            for (int j = 0; j < 4; ++j)
                *(uint2*)(vd + j * 8) = make_uint2(packh2(vst[j].x, vst[j].y),
                                                   packh2(vst[j].z, vst[j].w));
        }
    }

    // ---- epilogue ----
    const float inv0 = 1.0f / l0, inv1 = 1.0f / l1;
    float* op0 = ctx + qrow * D_M + h * DH;
    float* op1 = op0 + (size_t)8 * D_M;
    #pragma unroll
    for (int nt = 0; nt < 8; ++nt) {
        const int col = nt * 8 + tg * 2;
        *(float2*)(op0 + col) = make_float2(oacc[nt][0] * inv0, oacc[nt][1] * inv0);
        *(float2*)(op1 + col) = make_float2(oacc[nt][2] * inv1, oacc[nt][3] * inv1);
    }
}

// ---------------------------------------------------------------------------
// Launch
// ---------------------------------------------------------------------------
extern "C" void kernel_launch(void* const* d_in, const int* in_sizes, int n_in,
                              void* d_out, int out_size)
{
    (void)in_sizes; (void)n_in; (void)out_size;

    const float* query = (const float*)d_in[0];
    const int*   mask  = (const int*)  d_in[1];
    const float* Wq    = (const float*)d_in[2];
    const float* bq    = (const float*)d_in[3];
    const float* Wk    = (const float*)d_in[4];
    const float* bk    = (const float*)d_in[5];
    const float* Wv    = (const float*)d_in[6];
    const float* bv    = (const float*)d_in[7];
    const float* Wo    = (const float*)d_in[8];
    const float* bo    = (const float*)d_in[9];
    float* out = (float*)d_out;

    float *Qd, *Kd, *Vd, *Cd;
    cudaGetSymbolAddress((void**)&Qd, g_Q);
    cudaGetSymbolAddress((void**)&Kd, g_K);
    cudaGetSymbolAddress((void**)&Vd, g_V);
    cudaGetSymbolAddress((void**)&Cd, g_ctx);

    cudaFuncSetAttribute(sgemm_tf32_mma,
                         cudaFuncAttributeMaxDynamicSharedMemorySize,
                         GEMM_SMEM_BYTES);
    cudaFuncSetAttribute(flash_attn_f16,
                         cudaFuncAttributeMaxDynamicSharedMemorySize,
                         FA_SMEM_BYTES);

    dim3 gemm_grid(D_M / 128, MROWS / 128);  // (8, 64)

    sgemm_tf32_mma<<<gemm_grid, 256, GEMM_SMEM_BYTES>>>(query, Wq, bq, Qd);
    sgemm_tf32_mma<<<gemm_grid, 256, GEMM_SMEM_BYTES>>>(query, Wk, bk, Kd);
    sgemm_tf32_mma<<<gemm_grid, 256, GEMM_SMEM_BYTES>>>(query, Wv, bv, Vd);

    flash_attn_f16<<<dim3(T_S / 128, H_N, N_B), 256, FA_SMEM_BYTES>>>(
        Qd, Kd, Vd, mask, Cd);

    sgemm_tf32_mma<<<gemm_grid, 256, GEMM_SMEM_BYTES>>>(Cd, Wo, bo, out);
}